// round 11
// baseline (speedup 1.0000x reference)
#include <cuda_runtime.h>
#include <cstdint>

// ---------------------------------------------------------------------------
// SPNet, v10: single-block-per-batch SMEM-resident palette + fused
// gather/paint (unchanged, measured 29.3us @ 6.0 TB/s).
//
// Round-10 lesson: the palette kernel cost ~28us because h1/h2 round-tripped
// through global memory with inter-block flag spins. Entire chain now lives
// in dynamic SMEM (~176 KB/block), one 1024-thread block per batch, barriers
// only. 16 blocks = 1 wave.
// ---------------------------------------------------------------------------

#define BATCH    16
#define HW       160000         // 400*400
#define HW4      40000          // float4 per plane
#define GB_PER_B 157            // ceil(40000/256)
#define NGATHER  (BATCH * GB_PER_B)   // 2512
#define NTHREADS 256            // gather kernel
#define PTHREADS 1024           // palette kernel

// SMEM layout (float offsets)
#define OFF_SW1 0
#define OFF_SW2 162
#define OFF_SW3 810
#define OFF_SW4 2106
#define OFF_SW5 3402
#define OFF_SW6 4050
#define OFF_SB1 4068
#define OFF_SB2 4074
#define OFF_SB3 4086
#define OFF_SB4 4098
#define OFF_SB5 4110
#define OFF_SB6 4116
#define OFF_H1  4120                      // 6*64*64  = 24576
#define OFF_H2  (OFF_H1 + 24576)          // 12*32*32 = 12288
#define OFF_H3  (OFF_H2 + 12288)          // 12*16*16 = 3072
#define OFF_H4  (OFF_H3 + 3072)           // 12*8*8   = 768
#define OFF_H5  (OFF_H4 + 768)            // 6*16     = 96
#define SMEM_FLOATS (OFF_H5 + 96)         // 44920 floats = 179680 B

__device__ float g_pal[BATCH * 48];

__device__ __forceinline__ float leaky(float v) {
    return (v >= 0.f) ? v : 0.01f * v;
}

// ===========================================================================
// Kernel 1: palette. One 1024-thread block per batch, all stages in SMEM.
// ===========================================================================
__global__ void __launch_bounds__(PTHREADS, 1)
spnet_palette_kernel(const float* __restrict__ x,
                     const float* __restrict__ w1, const float* __restrict__ b1,
                     const float* __restrict__ w2, const float* __restrict__ b2,
                     const float* __restrict__ w3, const float* __restrict__ b3,
                     const float* __restrict__ w4, const float* __restrict__ b4,
                     const float* __restrict__ w5, const float* __restrict__ b5,
                     const float* __restrict__ w6, const float* __restrict__ b6) {
    extern __shared__ float s[];
    const int b   = blockIdx.x;
    const int tid = threadIdx.x;

    // stage all weights/biases
    for (int i = tid; i < 162; i += PTHREADS)  s[OFF_SW1 + i] = w1[i];
    for (int i = tid; i < 648; i += PTHREADS) { s[OFF_SW2 + i] = w2[i]; s[OFF_SW5 + i] = w5[i]; }
    for (int i = tid; i < 1296; i += PTHREADS) { s[OFF_SW3 + i] = w3[i]; s[OFF_SW4 + i] = w4[i]; }
    if (tid < 18) s[OFF_SW6 + tid] = w6[tid];
    if (tid < 12) { s[OFF_SB2 + tid] = b2[tid]; s[OFF_SB3 + tid] = b3[tid]; s[OFF_SB4 + tid] = b4[tid]; }
    if (tid < 6)  { s[OFF_SB1 + tid] = b1[tid]; s[OFF_SB5 + tid] = b5[tid]; }
    if (tid < 3)  s[OFF_SB6 + tid] = b6[tid];
    __syncthreads();

    // ---- conv1: x[3, 128x128 region] -> h1[6,64,64] (smem). 4 pos/thread.
#pragma unroll
    for (int rep = 0; rep < 4; rep++) {
        const int pos = rep * PTHREADS + tid;     // 0..4095
        const int i = pos >> 6;
        const int j = pos & 63;
        float acc[6];
#pragma unroll
        for (int oc = 0; oc < 6; oc++) acc[oc] = s[OFF_SB1 + oc];
#pragma unroll
        for (int ic = 0; ic < 3; ic++) {
            const float* xp = x + (size_t)(b * 3 + ic) * HW;
#pragma unroll
            for (int di = 0; di < 3; di++) {
                const int yi = 2 * i + di - 1;
#pragma unroll
                for (int dj = 0; dj < 3; dj++) {
                    const int yj = 2 * j + dj - 1;
                    float v = 0.f;
                    if (yi >= 0 && yj >= 0) v = __ldg(&xp[yi * 400 + yj]);
#pragma unroll
                    for (int oc = 0; oc < 6; oc++)
                        acc[oc] = fmaf(s[OFF_SW1 + (oc * 3 + ic) * 9 + di * 3 + dj], v, acc[oc]);
                }
            }
        }
#pragma unroll
        for (int oc = 0; oc < 6; oc++)
            s[OFF_H1 + (oc * 64 + i) * 64 + j] = leaky(acc[oc]);
    }
    __syncthreads();

    // ---- conv2: h1 -> h2[12,32,32]. 1024 positions, 1 per thread.
    {
        const int i = tid >> 5;
        const int j = tid & 31;
        float acc[12];
#pragma unroll
        for (int oc = 0; oc < 12; oc++) acc[oc] = s[OFF_SB2 + oc];
#pragma unroll
        for (int ic = 0; ic < 6; ic++) {
#pragma unroll
            for (int di = 0; di < 3; di++) {
                const int yi = 2 * i + di - 1;
#pragma unroll
                for (int dj = 0; dj < 3; dj++) {
                    const int yj = 2 * j + dj - 1;
                    float v = 0.f;
                    if (yi >= 0 && yj >= 0) v = s[OFF_H1 + (ic * 64 + yi) * 64 + yj];
#pragma unroll
                    for (int oc = 0; oc < 12; oc++)
                        acc[oc] = fmaf(s[OFF_SW2 + (oc * 6 + ic) * 9 + di * 3 + dj], v, acc[oc]);
                }
            }
        }
#pragma unroll
        for (int oc = 0; oc < 12; oc++)
            s[OFF_H2 + (oc * 32 + i) * 32 + j] = leaky(acc[oc]);
    }
    __syncthreads();

    // ---- conv3: h2 -> h3[12,16,16]. 256 threads.
    if (tid < 256) {
        const int i = tid >> 4;
        const int j = tid & 15;
        float acc[12];
#pragma unroll
        for (int oc = 0; oc < 12; oc++) acc[oc] = s[OFF_SB3 + oc];
        for (int ic = 0; ic < 12; ic++) {
#pragma unroll
            for (int di = 0; di < 3; di++) {
                const int yi = 2 * i + di - 1;
#pragma unroll
                for (int dj = 0; dj < 3; dj++) {
                    const int yj = 2 * j + dj - 1;
                    float v = 0.f;
                    if (yi >= 0 && yj >= 0) v = s[OFF_H2 + (ic * 32 + yi) * 32 + yj];
#pragma unroll
                    for (int oc = 0; oc < 12; oc++)
                        acc[oc] = fmaf(s[OFF_SW3 + (oc * 12 + ic) * 9 + di * 3 + dj], v, acc[oc]);
                }
            }
        }
#pragma unroll
        for (int oc = 0; oc < 12; oc++)
            s[OFF_H3 + (oc * 16 + i) * 16 + j] = leaky(acc[oc]);
    }
    __syncthreads();

    // ---- conv4: h3 -> h4[12,8,8]. 64 threads.
    if (tid < 64) {
        const int i = tid >> 3;
        const int j = tid & 7;
        float acc[12];
#pragma unroll
        for (int oc = 0; oc < 12; oc++) acc[oc] = s[OFF_SB4 + oc];
        for (int ic = 0; ic < 12; ic++) {
#pragma unroll
            for (int di = 0; di < 3; di++) {
                const int yi = 2 * i + di - 1;
#pragma unroll
                for (int dj = 0; dj < 3; dj++) {
                    const int yj = 2 * j + dj - 1;
                    float v = 0.f;
                    if (yi >= 0 && yj >= 0) v = s[OFF_H3 + (ic * 16 + yi) * 16 + yj];
#pragma unroll
                    for (int oc = 0; oc < 12; oc++)
                        acc[oc] = fmaf(s[OFF_SW4 + (oc * 12 + ic) * 9 + di * 3 + dj], v, acc[oc]);
                }
            }
        }
#pragma unroll
        for (int oc = 0; oc < 12; oc++)
            s[OFF_H4 + (oc * 8 + i) * 8 + j] = leaky(acc[oc]);
    }
    __syncthreads();

    // ---- conv5: h4 -> h5[6,4,4]. 96 threads.
    if (tid < 96) {
        const int oc = tid >> 4;
        const int p  = tid & 15;
        const int i  = p >> 2;
        const int jj = p & 3;
        float acc = s[OFF_SB5 + oc];
        for (int ic = 0; ic < 12; ic++) {
#pragma unroll
            for (int di = 0; di < 3; di++) {
                const int yi = 2 * i + di - 1;
#pragma unroll
                for (int dj = 0; dj < 3; dj++) {
                    const int yj = 2 * jj + dj - 1;
                    float v = 0.f;
                    if (yi >= 0 && yj >= 0) v = s[OFF_H4 + (ic * 8 + yi) * 8 + yj];
                    acc = fmaf(s[OFF_SW5 + (oc * 12 + ic) * 9 + di * 3 + dj], v, acc);
                }
            }
        }
        s[OFF_H5 + oc * 16 + p] = leaky(acc);
    }
    __syncthreads();

    // ---- conv6 (1x1) + relu -> g_pal (gather kernel is stream-ordered)
    if (tid < 48) {
        const int c = tid >> 4;
        const int k = tid & 15;
        float acc = s[OFF_SB6 + c];
#pragma unroll
        for (int ic = 0; ic < 6; ic++)
            acc = fmaf(s[OFF_SW6 + c * 6 + ic], s[OFF_H5 + ic * 16 + k], acc);
        g_pal[b * 48 + c * 16 + k] = fmaxf(acc, 0.f);
    }
}

// ===========================================================================
// Kernel 2: fused gather + paint (unchanged; 29.3us @ 6.0 TB/s measured).
// ===========================================================================
__global__ void __launch_bounds__(NTHREADS, 2)
spnet_gather_paint_kernel(const float* __restrict__ logits,
                          float* __restrict__ out) {
    const int gid = blockIdx.x;
    const int b   = gid / GB_PER_B;
    const int blk = gid - b * GB_PER_B;
    const int p   = blk * NTHREADS + threadIdx.x;
    const bool act = (p < HW4);

    __shared__ float4 spal4[16];

    float4 l[16];
    if (act) {
        const float4* lg = reinterpret_cast<const float4*>(logits)
                           + (size_t)b * 16 * HW4 + p;
#pragma unroll
        for (int k = 0; k < 16; k++) l[k] = __ldcs(lg + (size_t)k * HW4);
    }

    if (threadIdx.x < 16) {
        const int k = threadIdx.x;
        spal4[k] = make_float4(g_pal[b * 48 + k],
                               g_pal[b * 48 + 16 + k],
                               g_pal[b * 48 + 32 + k],
                               0.f);
    }
    __syncthreads();

    if (!act) return;

    float4 mx = l[0];
#pragma unroll
    for (int k = 1; k < 16; k++) {
        mx.x = fmaxf(mx.x, l[k].x);
        mx.y = fmaxf(mx.y, l[k].y);
        mx.z = fmaxf(mx.z, l[k].z);
        mx.w = fmaxf(mx.w, l[k].w);
    }

    unsigned mA = 0, mB = 0, mC = 0, mD = 0;
#pragma unroll
    for (int k = 0; k < 16; k++) {
        mA |= (l[k].x == mx.x) ? (1u << k) : 0u;
        mB |= (l[k].y == mx.y) ? (1u << k) : 0u;
        mC |= (l[k].z == mx.z) ? (1u << k) : 0u;
        mD |= (l[k].w == mx.w) ? (1u << k) : 0u;
    }

    float r0[4], r1[4], r2[4];
    unsigned ms[4] = { mA, mB, mC, mD };
#pragma unroll
    for (int px = 0; px < 4; px++) {
        unsigned bits = ms[px];
        float s0 = 0.f, s1 = 0.f, s2 = 0.f;
        while (bits) {
            const int k = __ffs(bits) - 1;
            bits &= bits - 1;
            const float4 c = spal4[k];
            s0 += c.x; s1 += c.y; s2 += c.z;
        }
        r0[px] = s0; r1[px] = s1; r2[px] = s2;
    }

    float4* o = reinterpret_cast<float4*>(out) + (size_t)(b * 3) * HW4 + p;
    __stcs(o,                   make_float4(r0[0], r0[1], r0[2], r0[3]));
    __stcs(o + HW4,             make_float4(r1[0], r1[1], r1[2], r1[3]));
    __stcs(o + 2 * (size_t)HW4, make_float4(r2[0], r2[1], r2[2], r2[3]));
}

// ---------------------------------------------------------------------------
extern "C" void kernel_launch(void* const* d_in, const int* in_sizes, int n_in,
                              void* d_out, int out_size) {
    (void)in_sizes; (void)n_in; (void)out_size;
    const float* x  = (const float*)d_in[0];
    const float* bl = (const float*)d_in[1];
    const float* w1 = (const float*)d_in[2];
    const float* b1 = (const float*)d_in[3];
    const float* w2 = (const float*)d_in[4];
    const float* b2 = (const float*)d_in[5];
    const float* w3 = (const float*)d_in[6];
    const float* b3 = (const float*)d_in[7];
    const float* w4 = (const float*)d_in[8];
    const float* b4 = (const float*)d_in[9];
    const float* w5 = (const float*)d_in[10];
    const float* b5 = (const float*)d_in[11];
    const float* w6 = (const float*)d_in[12];
    const float* b6 = (const float*)d_in[13];
    float* out = (float*)d_out;

    const int smem_bytes = SMEM_FLOATS * (int)sizeof(float);   // ~175.5 KB
    cudaFuncSetAttribute(spnet_palette_kernel,
                         cudaFuncAttributeMaxDynamicSharedMemorySize, smem_bytes);

    spnet_palette_kernel<<<BATCH, PTHREADS, smem_bytes>>>(
        x, w1, b1, w2, b2, w3, b3, w4, b4, w5, b5, w6, b6);
    spnet_gather_paint_kernel<<<NGATHER, NTHREADS>>>(bl, out);
}

// round 12
// speedup vs baseline: 1.0068x; 1.0068x over previous
#include <cuda_runtime.h>
#include <cstdint>

// ---------------------------------------------------------------------------
// SPNet, v11: wide stream-ordered conv chain + fused gather/paint.
//
// Round-11 lesson: palette cost is INSTRUCTION ISSUE (~120k warp-instr/block)
// on too few SMs, not memory locality. Split conv into 3 small stream-ordered
// kernels across 128/64/16 blocks (graph launches ~1us each, no flags).
// Gather kernel unchanged except occupancy 2->3 blocks/SM (76 regs fits).
// ---------------------------------------------------------------------------

#define BATCH    16
#define HW       160000         // 400*400
#define HW4      40000          // float4 per plane
#define GB_PER_B 157            // ceil(40000/256)
#define NGATHER  (BATCH * GB_PER_B)   // 2512

__device__ float g_h1[BATCH * 6  * 64 * 64];
__device__ float g_h2[BATCH * 12 * 32 * 32];
__device__ float g_pal[BATCH * 48];

__device__ __forceinline__ float leaky(float v) {
    return (v >= 0.f) ? v : 0.01f * v;
}

// ===========================================================================
// K1: conv1. grid (8 strips, 16 batch) x 256 thr; 2 positions per thread.
// x[b, 0:3, -1..127, -1..127] -> h1[b, 0:6, 64, 64]
// ===========================================================================
__global__ void __launch_bounds__(256)
conv1_kernel(const float* __restrict__ x,
             const float* __restrict__ w1, const float* __restrict__ b1) {
    const int b = blockIdx.y;
    const int s = blockIdx.x;           // 0..7 (8-row strips)
    const int tid = threadIdx.x;

    __shared__ float sw[162], sb[6];
    if (tid < 162) sw[tid] = w1[tid];
    if (tid < 6)   sb[tid] = b1[tid];
    __syncthreads();

#pragma unroll
    for (int rep = 0; rep < 2; rep++) {
        const int pos = rep * 256 + tid;          // 0..511
        const int i = s * 8 + (pos >> 6);
        const int j = pos & 63;
        float acc[6];
#pragma unroll
        for (int oc = 0; oc < 6; oc++) acc[oc] = sb[oc];
#pragma unroll
        for (int ic = 0; ic < 3; ic++) {
            const float* xp = x + (size_t)(b * 3 + ic) * HW;
#pragma unroll
            for (int di = 0; di < 3; di++) {
                const int yi = 2 * i + di - 1;
#pragma unroll
                for (int dj = 0; dj < 3; dj++) {
                    const int yj = 2 * j + dj - 1;
                    float v = 0.f;
                    if (yi >= 0 && yj >= 0) v = __ldg(&xp[yi * 400 + yj]);
#pragma unroll
                    for (int oc = 0; oc < 6; oc++)
                        acc[oc] = fmaf(sw[(oc * 3 + ic) * 9 + di * 3 + dj], v, acc[oc]);
                }
            }
        }
#pragma unroll
        for (int oc = 0; oc < 6; oc++)
            g_h1[((b * 6 + oc) * 64 + i) * 64 + j] = leaky(acc[oc]);
    }
}

// ===========================================================================
// K2: conv2. grid (4 strips, 16 batch) x 256 thr; 1 position, 12 oc.
// h1 (L2-hot) -> h2[b, 0:12, 32, 32]
// ===========================================================================
__global__ void __launch_bounds__(256)
conv2_kernel(const float* __restrict__ w2, const float* __restrict__ b2) {
    const int b = blockIdx.y;
    const int s = blockIdx.x;           // 0..3 (8-row strips)
    const int tid = threadIdx.x;

    __shared__ float sw[648], sb[12];
    for (int i = tid; i < 648; i += 256) sw[i] = w2[i];
    if (tid < 12) sb[tid] = b2[tid];
    __syncthreads();

    const int i = s * 8 + (tid >> 5);
    const int j = tid & 31;
    const float* h1b = g_h1 + (size_t)b * 6 * 64 * 64;

    float acc[12];
#pragma unroll
    for (int oc = 0; oc < 12; oc++) acc[oc] = sb[oc];
#pragma unroll
    for (int ic = 0; ic < 6; ic++) {
#pragma unroll
        for (int di = 0; di < 3; di++) {
            const int yi = 2 * i + di - 1;
#pragma unroll
            for (int dj = 0; dj < 3; dj++) {
                const int yj = 2 * j + dj - 1;
                float v = 0.f;
                if (yi >= 0 && yj >= 0) v = __ldg(&h1b[(ic * 64 + yi) * 64 + yj]);
#pragma unroll
                for (int oc = 0; oc < 12; oc++)
                    acc[oc] = fmaf(sw[(oc * 6 + ic) * 9 + di * 3 + dj], v, acc[oc]);
            }
        }
    }
#pragma unroll
    for (int oc = 0; oc < 12; oc++)
        g_h2[((b * 12 + oc) * 32 + i) * 32 + j] = leaky(acc[oc]);
}

// ===========================================================================
// K3: conv3..6 fused. 16 blocks x 512 thr. oc split across thread halves.
// ===========================================================================
__global__ void __launch_bounds__(512)
conv_tail_kernel(const float* __restrict__ w3, const float* __restrict__ b3,
                 const float* __restrict__ w4, const float* __restrict__ b4,
                 const float* __restrict__ w5, const float* __restrict__ b5,
                 const float* __restrict__ w6, const float* __restrict__ b6) {
    const int b   = blockIdx.x;
    const int tid = threadIdx.x;    // 512

    __shared__ float sw3[1296], sw4[1296], sw5[648], sw6[18];
    __shared__ float sb3[12], sb4[12], sb5[6], sb6[3];
    __shared__ float h3[12 * 16 * 16];
    __shared__ float h4[12 * 8 * 8];
    __shared__ float h5[6 * 16];

    for (int i = tid; i < 1296; i += 512) { sw3[i] = w3[i]; sw4[i] = w4[i]; }
    for (int i = tid; i < 648;  i += 512) sw5[i] = w5[i];
    if (tid < 18) sw6[tid] = w6[tid];
    if (tid < 12) { sb3[tid] = b3[tid]; sb4[tid] = b4[tid]; }
    if (tid < 6)  sb5[tid] = b5[tid];
    if (tid < 3)  sb6[tid] = b6[tid];
    __syncthreads();

    // ---- conv3: 512 threads = (half, i, j); 6 oc each. h2 from global (L2).
    {
        const int half = tid >> 8;         // 0..1
        const int pos  = tid & 255;
        const int i = pos >> 4;
        const int j = pos & 15;
        const float* h2b = g_h2 + (size_t)b * 12 * 32 * 32;
        float acc[6];
#pragma unroll
        for (int oc = 0; oc < 6; oc++) acc[oc] = sb3[half * 6 + oc];
        for (int ic = 0; ic < 12; ic++) {
#pragma unroll
            for (int di = 0; di < 3; di++) {
                const int yi = 2 * i + di - 1;
#pragma unroll
                for (int dj = 0; dj < 3; dj++) {
                    const int yj = 2 * j + dj - 1;
                    float v = 0.f;
                    if (yi >= 0 && yj >= 0) v = __ldg(&h2b[(ic * 32 + yi) * 32 + yj]);
#pragma unroll
                    for (int oc = 0; oc < 6; oc++)
                        acc[oc] = fmaf(sw3[((half * 6 + oc) * 12 + ic) * 9 + di * 3 + dj],
                                       v, acc[oc]);
                }
            }
        }
#pragma unroll
        for (int oc = 0; oc < 6; oc++)
            h3[((half * 6 + oc) * 16 + i) * 16 + j] = leaky(acc[oc]);
    }
    __syncthreads();

    // ---- conv4: 128 threads = (half, i, j); 6 oc each.
    if (tid < 128) {
        const int half = tid >> 6;
        const int pos  = tid & 63;
        const int i = pos >> 3;
        const int j = pos & 7;
        float acc[6];
#pragma unroll
        for (int oc = 0; oc < 6; oc++) acc[oc] = sb4[half * 6 + oc];
        for (int ic = 0; ic < 12; ic++) {
#pragma unroll
            for (int di = 0; di < 3; di++) {
                const int yi = 2 * i + di - 1;
#pragma unroll
                for (int dj = 0; dj < 3; dj++) {
                    const int yj = 2 * j + dj - 1;
                    float v = 0.f;
                    if (yi >= 0 && yj >= 0) v = h3[(ic * 16 + yi) * 16 + yj];
#pragma unroll
                    for (int oc = 0; oc < 6; oc++)
                        acc[oc] = fmaf(sw4[((half * 6 + oc) * 12 + ic) * 9 + di * 3 + dj],
                                       v, acc[oc]);
                }
            }
        }
#pragma unroll
        for (int oc = 0; oc < 6; oc++)
            h4[((half * 6 + oc) * 8 + i) * 8 + j] = leaky(acc[oc]);
    }
    __syncthreads();

    // ---- conv5: 96 threads.
    if (tid < 96) {
        const int oc = tid >> 4;
        const int p  = tid & 15;
        const int i  = p >> 2;
        const int jj = p & 3;
        float acc = sb5[oc];
        for (int ic = 0; ic < 12; ic++) {
#pragma unroll
            for (int di = 0; di < 3; di++) {
                const int yi = 2 * i + di - 1;
#pragma unroll
                for (int dj = 0; dj < 3; dj++) {
                    const int yj = 2 * jj + dj - 1;
                    float v = 0.f;
                    if (yi >= 0 && yj >= 0) v = h4[(ic * 8 + yi) * 8 + yj];
                    acc = fmaf(sw5[(oc * 12 + ic) * 9 + di * 3 + dj], v, acc);
                }
            }
        }
        h5[oc * 16 + p] = leaky(acc);
    }
    __syncthreads();

    // ---- conv6 (1x1) + relu -> g_pal (gather kernel is stream-ordered)
    if (tid < 48) {
        const int c = tid >> 4;
        const int k = tid & 15;
        float acc = sb6[c];
#pragma unroll
        for (int ic = 0; ic < 6; ic++)
            acc = fmaf(sw6[c * 6 + ic], h5[ic * 16 + k], acc);
        g_pal[b * 48 + c * 16 + k] = fmaxf(acc, 0.f);
    }
}

// ===========================================================================
// K4: fused gather + paint (same code as the 29.3us/6.0TB/s version;
// occupancy raised to 3 blocks/SM — 76 regs x 768 thr fits the RF).
// ===========================================================================
__global__ void __launch_bounds__(256, 3)
spnet_gather_paint_kernel(const float* __restrict__ logits,
                          float* __restrict__ out) {
    const int gid = blockIdx.x;
    const int b   = gid / GB_PER_B;
    const int blk = gid - b * GB_PER_B;
    const int p   = blk * 256 + threadIdx.x;
    const bool act = (p < HW4);

    __shared__ float4 spal4[16];

    float4 l[16];
    if (act) {
        const float4* lg = reinterpret_cast<const float4*>(logits)
                           + (size_t)b * 16 * HW4 + p;
#pragma unroll
        for (int k = 0; k < 16; k++) l[k] = __ldcs(lg + (size_t)k * HW4);
    }

    if (threadIdx.x < 16) {
        const int k = threadIdx.x;
        spal4[k] = make_float4(g_pal[b * 48 + k],
                               g_pal[b * 48 + 16 + k],
                               g_pal[b * 48 + 32 + k],
                               0.f);
    }
    __syncthreads();

    if (!act) return;

    float4 mx = l[0];
#pragma unroll
    for (int k = 1; k < 16; k++) {
        mx.x = fmaxf(mx.x, l[k].x);
        mx.y = fmaxf(mx.y, l[k].y);
        mx.z = fmaxf(mx.z, l[k].z);
        mx.w = fmaxf(mx.w, l[k].w);
    }

    unsigned mA = 0, mB = 0, mC = 0, mD = 0;
#pragma unroll
    for (int k = 0; k < 16; k++) {
        mA |= (l[k].x == mx.x) ? (1u << k) : 0u;
        mB |= (l[k].y == mx.y) ? (1u << k) : 0u;
        mC |= (l[k].z == mx.z) ? (1u << k) : 0u;
        mD |= (l[k].w == mx.w) ? (1u << k) : 0u;
    }

    float r0[4], r1[4], r2[4];
    unsigned ms[4] = { mA, mB, mC, mD };
#pragma unroll
    for (int px = 0; px < 4; px++) {
        unsigned bits = ms[px];
        float s0 = 0.f, s1 = 0.f, s2 = 0.f;
        while (bits) {
            const int k = __ffs(bits) - 1;
            bits &= bits - 1;
            const float4 c = spal4[k];
            s0 += c.x; s1 += c.y; s2 += c.z;
        }
        r0[px] = s0; r1[px] = s1; r2[px] = s2;
    }

    float4* o = reinterpret_cast<float4*>(out) + (size_t)(b * 3) * HW4 + p;
    __stcs(o,                   make_float4(r0[0], r0[1], r0[2], r0[3]));
    __stcs(o + HW4,             make_float4(r1[0], r1[1], r1[2], r1[3]));
    __stcs(o + 2 * (size_t)HW4, make_float4(r2[0], r2[1], r2[2], r2[3]));
}

// ---------------------------------------------------------------------------
extern "C" void kernel_launch(void* const* d_in, const int* in_sizes, int n_in,
                              void* d_out, int out_size) {
    (void)in_sizes; (void)n_in; (void)out_size;
    const float* x  = (const float*)d_in[0];
    const float* bl = (const float*)d_in[1];
    const float* w1 = (const float*)d_in[2];
    const float* b1 = (const float*)d_in[3];
    const float* w2 = (const float*)d_in[4];
    const float* b2 = (const float*)d_in[5];
    const float* w3 = (const float*)d_in[6];
    const float* b3 = (const float*)d_in[7];
    const float* w4 = (const float*)d_in[8];
    const float* b4 = (const float*)d_in[9];
    const float* w5 = (const float*)d_in[10];
    const float* b5 = (const float*)d_in[11];
    const float* w6 = (const float*)d_in[12];
    const float* b6 = (const float*)d_in[13];
    float* out = (float*)d_out;

    conv1_kernel<<<dim3(8, BATCH), 256>>>(x, w1, b1);
    conv2_kernel<<<dim3(4, BATCH), 256>>>(w2, b2);
    conv_tail_kernel<<<BATCH, 512>>>(w3, b3, w4, b4, w5, b5, w6, b6);
    spnet_gather_paint_kernel<<<NGATHER, 256>>>(bl, out);
}

// round 13
// speedup vs baseline: 1.3217x; 1.3128x over previous
#include <cuda_runtime.h>
#include <cstdint>

// ---------------------------------------------------------------------------
// SPNet, v12: round-9 hybrid (conv inside gather kernel, inline paint when
// palette ready) + COMPACTED leftover-paint queue.
//
// Round-12 lesson: serial conv chain costs ~31us no matter how it's
// structured; only the round-9 embedding hides it. Round-9's weak spot was
// the leftover paint kernel: 2512 mostly-empty blocks = ~9 waves of launch
// churn (11.2us). Now blocks that miss the palette push their gid to a
// queue; paint is ONE wave of 1024 persistent blocks striding the queue.
// ---------------------------------------------------------------------------

#define BATCH    16
#define HW       160000         // 400*400
#define HW4      40000          // float4 per plane
#define GB_PER_B 157            // ceil(40000/256)
#define NGATHER  (BATCH * GB_PER_B)   // 2512
#define NCONVBLK 64
#define NTHREADS 256
#define NPAINT   1024           // paint kernel grid (single wave)

__device__ float              g_h1[BATCH * 6  * 64 * 64];
__device__ float              g_h2[BATCH * 12 * 32 * 32];
__device__ float              g_pal[BATCH * 48];
__device__ unsigned long long g_mask[BATCH * HW4];
// g_sync: [0:16) conv1 count, [16:32) conv2 count, [32:48) pal-ready,
//         [48] queue counter.
__device__ unsigned           g_sync[49];
__device__ int                g_queue[NGATHER];

__device__ __forceinline__ float leaky(float v) {
    return (v >= 0.f) ? v : 0.01f * v;
}

// ===========================================================================
// Kernel 1: blocks 0..63 conv pipeline; blocks 64.. gather (inline paint or
// mask+enqueue).
// ===========================================================================
__global__ void __launch_bounds__(NTHREADS, 2)
spnet_main_kernel(const float* __restrict__ x,
                  const float* __restrict__ logits,
                  const float* __restrict__ w1, const float* __restrict__ b1,
                  const float* __restrict__ w2, const float* __restrict__ b2,
                  const float* __restrict__ w3, const float* __restrict__ b3,
                  const float* __restrict__ w4, const float* __restrict__ b4,
                  const float* __restrict__ w5, const float* __restrict__ b5,
                  const float* __restrict__ w6, const float* __restrict__ b6,
                  float* __restrict__ out) {
    const int bid = blockIdx.x;
    const int tid = threadIdx.x;

    // ---------------------------------------------------------------------
    // CONV PATH (b = bid>>2, q = bid&3) — identical to round 9.
    // ---------------------------------------------------------------------
    if (bid < NCONVBLK) {
        const int b = bid >> 2;
        const int q = bid & 3;

        __shared__ float sw1[162], sb1[6];
        __shared__ float sw2[648], sb2[12];
        __shared__ float sw3[1296], sb3[12];
        __shared__ float sw4[1296], sb4[12];
        __shared__ float sw5[648], sb5[6];
        __shared__ float sw6[18], sb6[3];
        __shared__ float h3[12 * 16 * 16];
        __shared__ float h4[12 * 8 * 8];
        __shared__ float h5[6 * 16];

        for (int i = tid; i < 162; i += NTHREADS) sw1[i] = w1[i];
        for (int i = tid; i < 648; i += NTHREADS) { sw2[i] = w2[i]; sw5[i] = w5[i]; }
        for (int i = tid; i < 1296; i += NTHREADS) { sw3[i] = w3[i]; sw4[i] = w4[i]; }
        if (tid < 18) sw6[tid] = w6[tid];
        if (tid < 12) { sb2[tid] = b2[tid]; sb3[tid] = b3[tid]; sb4[tid] = b4[tid]; }
        if (tid < 6)  { sb1[tid] = b1[tid]; sb5[tid] = b5[tid]; }
        if (tid < 3)  sb6[tid] = b6[tid];
        __syncthreads();

        // conv1, quarter q
        for (int pos = tid; pos < 1024; pos += NTHREADS) {
            const int i = q * 16 + (pos >> 6);
            const int j = pos & 63;
            float acc[6];
#pragma unroll
            for (int oc = 0; oc < 6; oc++) acc[oc] = sb1[oc];
#pragma unroll
            for (int ic = 0; ic < 3; ic++) {
                const float* xp = x + (size_t)(b * 3 + ic) * HW;
#pragma unroll
                for (int di = 0; di < 3; di++) {
                    const int yi = 2 * i + di - 1;
#pragma unroll
                    for (int dj = 0; dj < 3; dj++) {
                        const int yj = 2 * j + dj - 1;
                        float v = 0.f;
                        if (yi >= 0 && yj >= 0) v = xp[yi * 400 + yj];
#pragma unroll
                        for (int oc = 0; oc < 6; oc++)
                            acc[oc] = fmaf(sw1[(oc * 3 + ic) * 9 + di * 3 + dj], v, acc[oc]);
                    }
                }
            }
#pragma unroll
            for (int oc = 0; oc < 6; oc++)
                g_h1[((b * 6 + oc) * 64 + i) * 64 + j] = leaky(acc[oc]);
        }
        __threadfence();
        __syncthreads();
        if (tid == 0) atomicAdd(&g_sync[b], 1u);

        if (tid == 0) {
            while (atomicAdd(&g_sync[b], 0u) < 4u) __nanosleep(64);
            __threadfence();
        }
        __syncthreads();

        // conv2, quarter q
        {
            const int i = q * 8 + (tid >> 5);
            const int j = tid & 31;
            const float* h1b = g_h1 + (size_t)b * 6 * 64 * 64;
            float acc[12];
#pragma unroll
            for (int oc = 0; oc < 12; oc++) acc[oc] = sb2[oc];
#pragma unroll
            for (int ic = 0; ic < 6; ic++) {
#pragma unroll
                for (int di = 0; di < 3; di++) {
                    const int yi = 2 * i + di - 1;
#pragma unroll
                    for (int dj = 0; dj < 3; dj++) {
                        const int yj = 2 * j + dj - 1;
                        float v = 0.f;
                        if (yi >= 0 && yj >= 0) v = h1b[(ic * 64 + yi) * 64 + yj];
#pragma unroll
                        for (int oc = 0; oc < 12; oc++)
                            acc[oc] = fmaf(sw2[(oc * 6 + ic) * 9 + di * 3 + dj], v, acc[oc]);
                    }
                }
            }
#pragma unroll
            for (int oc = 0; oc < 12; oc++)
                g_h2[((b * 12 + oc) * 32 + i) * 32 + j] = leaky(acc[oc]);
        }
        __threadfence();
        __syncthreads();
        if (tid == 0) atomicAdd(&g_sync[16 + b], 1u);

        if (q != 0) return;

        if (tid == 0) {
            while (atomicAdd(&g_sync[16 + b], 0u) < 4u) __nanosleep(64);
            __threadfence();
        }
        __syncthreads();

        // conv3
        {
            const int i = tid >> 4;
            const int j = tid & 15;
            const float* h2b = g_h2 + (size_t)b * 12 * 32 * 32;
            float acc[12];
#pragma unroll
            for (int oc = 0; oc < 12; oc++) acc[oc] = sb3[oc];
            for (int ic = 0; ic < 12; ic++) {
#pragma unroll
                for (int di = 0; di < 3; di++) {
                    const int yi = 2 * i + di - 1;
#pragma unroll
                    for (int dj = 0; dj < 3; dj++) {
                        const int yj = 2 * j + dj - 1;
                        float v = 0.f;
                        if (yi >= 0 && yj >= 0) v = h2b[(ic * 32 + yi) * 32 + yj];
#pragma unroll
                        for (int oc = 0; oc < 12; oc++)
                            acc[oc] = fmaf(sw3[(oc * 12 + ic) * 9 + di * 3 + dj], v, acc[oc]);
                    }
                }
            }
#pragma unroll
            for (int oc = 0; oc < 12; oc++)
                h3[(oc * 16 + i) * 16 + j] = leaky(acc[oc]);
        }
        __syncthreads();

        // conv4
        if (tid < 64) {
            const int i = tid >> 3;
            const int j = tid & 7;
            float acc[12];
#pragma unroll
            for (int oc = 0; oc < 12; oc++) acc[oc] = sb4[oc];
            for (int ic = 0; ic < 12; ic++) {
#pragma unroll
                for (int di = 0; di < 3; di++) {
                    const int yi = 2 * i + di - 1;
#pragma unroll
                    for (int dj = 0; dj < 3; dj++) {
                        const int yj = 2 * j + dj - 1;
                        float v = 0.f;
                        if (yi >= 0 && yj >= 0) v = h3[(ic * 16 + yi) * 16 + yj];
#pragma unroll
                        for (int oc = 0; oc < 12; oc++)
                            acc[oc] = fmaf(sw4[(oc * 12 + ic) * 9 + di * 3 + dj], v, acc[oc]);
                    }
                }
            }
#pragma unroll
            for (int oc = 0; oc < 12; oc++)
                h4[(oc * 8 + i) * 8 + j] = leaky(acc[oc]);
        }
        __syncthreads();

        // conv5
        if (tid < 96) {
            const int oc = tid >> 4;
            const int p  = tid & 15;
            const int i  = p >> 2;
            const int jj = p & 3;
            float acc = sb5[oc];
            for (int ic = 0; ic < 12; ic++) {
#pragma unroll
                for (int di = 0; di < 3; di++) {
                    const int yi = 2 * i + di - 1;
#pragma unroll
                    for (int dj = 0; dj < 3; dj++) {
                        const int yj = 2 * jj + dj - 1;
                        float v = 0.f;
                        if (yi >= 0 && yj >= 0) v = h4[(ic * 8 + yi) * 8 + yj];
                        acc = fmaf(sw5[(oc * 12 + ic) * 9 + di * 3 + dj], v, acc);
                    }
                }
            }
            h5[oc * 16 + p] = leaky(acc);
        }
        __syncthreads();

        // conv6 (1x1) + relu -> g_pal, publish pal-ready
        if (tid < 48) {
            const int c = tid >> 4;
            const int k = tid & 15;
            float acc = sb6[c];
#pragma unroll
            for (int ic = 0; ic < 6; ic++)
                acc = fmaf(sw6[c * 6 + ic], h5[ic * 16 + k], acc);
            g_pal[b * 48 + c * 16 + k] = fmaxf(acc, 0.f);
            __threadfence();
        }
        __syncthreads();
        if (tid == 0) atomicExch(&g_sync[32 + b], 1u);
        return;
    }

    // ---------------------------------------------------------------------
    // GATHER PATH: loads first, non-blocking palette check, inline paint
    // or mask+enqueue.
    // ---------------------------------------------------------------------
    const int gid = bid - NCONVBLK;
    const int b   = gid / GB_PER_B;
    const int blk = gid - b * GB_PER_B;
    const int p   = blk * NTHREADS + tid;
    const bool act = (p < HW4);

    __shared__ float4   spal4[16];
    __shared__ unsigned s_ready;

    float4 l[16];
    if (act) {
        const float4* lg = reinterpret_cast<const float4*>(logits)
                           + (size_t)b * 16 * HW4 + p;
#pragma unroll
        for (int k = 0; k < 16; k++) l[k] = __ldcs(lg + (size_t)k * HW4);
    }

    if (tid == 0) {
        const unsigned r = atomicAdd(&g_sync[32 + b], 0u);
        if (r) __threadfence();
        s_ready = r;
    }
    __syncthreads();
    const bool direct = (s_ready != 0u);
    if (direct && tid < 16) {
        const int k = tid;
        spal4[k] = make_float4(__ldcg(&g_pal[b * 48 + k]),
                               __ldcg(&g_pal[b * 48 + 16 + k]),
                               __ldcg(&g_pal[b * 48 + 32 + k]),
                               0.f);
    }
    __syncthreads();

    if (act) {
        float4 mx = l[0];
#pragma unroll
        for (int k = 1; k < 16; k++) {
            mx.x = fmaxf(mx.x, l[k].x);
            mx.y = fmaxf(mx.y, l[k].y);
            mx.z = fmaxf(mx.z, l[k].z);
            mx.w = fmaxf(mx.w, l[k].w);
        }

        unsigned mA = 0, mB = 0, mC = 0, mD = 0;
#pragma unroll
        for (int k = 0; k < 16; k++) {
            mA |= (l[k].x == mx.x) ? (1u << k) : 0u;
            mB |= (l[k].y == mx.y) ? (1u << k) : 0u;
            mC |= (l[k].z == mx.z) ? (1u << k) : 0u;
            mD |= (l[k].w == mx.w) ? (1u << k) : 0u;
        }

        if (direct) {
            float r0[4], r1[4], r2[4];
            unsigned ms[4] = { mA, mB, mC, mD };
#pragma unroll
            for (int px = 0; px < 4; px++) {
                unsigned bits = ms[px];
                float s0 = 0.f, s1 = 0.f, s2 = 0.f;
                while (bits) {
                    const int k = __ffs(bits) - 1;
                    bits &= bits - 1;
                    const float4 c = spal4[k];
                    s0 += c.x; s1 += c.y; s2 += c.z;
                }
                r0[px] = s0; r1[px] = s1; r2[px] = s2;
            }
            float4* o = reinterpret_cast<float4*>(out) + (size_t)(b * 3) * HW4 + p;
            __stcs(o,                    make_float4(r0[0], r0[1], r0[2], r0[3]));
            __stcs(o + HW4,              make_float4(r1[0], r1[1], r1[2], r1[3]));
            __stcs(o + 2 * (size_t)HW4,  make_float4(r2[0], r2[1], r2[2], r2[3]));
        } else {
            const unsigned long long m =
                (unsigned long long)mA
                | ((unsigned long long)mB << 16)
                | ((unsigned long long)mC << 32)
                | ((unsigned long long)mD << 48);
            g_mask[(size_t)b * HW4 + p] = m;
        }
    }

    // enqueue this block for the paint pass if palette wasn't ready
    if (!direct && tid == 0) {
        const unsigned idx = atomicAdd(&g_sync[48], 1u);
        g_queue[idx] = gid;
    }
}

// ===========================================================================
// Kernel 2: paint leftovers. Single wave of persistent blocks striding the
// compact queue (n entries, typically ~700).
// ===========================================================================
__global__ void __launch_bounds__(NTHREADS)
spnet_paint_kernel(float* __restrict__ out) {
    __shared__ float4 spal4[16];

    const int n = (int)g_sync[48];   // fixed after kernel 1 (stream order)

    for (int e = blockIdx.x; e < n; e += NPAINT) {
        const int gid = g_queue[e];
        const int b   = gid / GB_PER_B;
        const int blk = gid - b * GB_PER_B;
        const int p   = blk * NTHREADS + threadIdx.x;

        __syncthreads();   // protect spal4 reuse across iterations
        if (threadIdx.x < 16) {
            const int k = threadIdx.x;
            spal4[k] = make_float4(g_pal[b * 48 + k],
                                   g_pal[b * 48 + 16 + k],
                                   g_pal[b * 48 + 32 + k],
                                   0.f);
        }
        __syncthreads();

        if (p >= HW4) continue;

        const unsigned long long m = g_mask[(size_t)b * HW4 + p];

        float r0[4], r1[4], r2[4];
#pragma unroll
        for (int px = 0; px < 4; px++) {
            unsigned bits = (unsigned)((m >> (16 * px)) & 0xFFFFull);
            float s0 = 0.f, s1 = 0.f, s2 = 0.f;
            while (bits) {
                const int k = __ffs(bits) - 1;
                bits &= bits - 1;
                const float4 c = spal4[k];
                s0 += c.x; s1 += c.y; s2 += c.z;
            }
            r0[px] = s0; r1[px] = s1; r2[px] = s2;
        }

        float4* o = reinterpret_cast<float4*>(out) + (size_t)(b * 3) * HW4 + p;
        o[0]               = make_float4(r0[0], r0[1], r0[2], r0[3]);
        o[HW4]             = make_float4(r1[0], r1[1], r1[2], r1[3]);
        o[2 * (size_t)HW4] = make_float4(r2[0], r2[1], r2[2], r2[3]);
    }
}

// ---------------------------------------------------------------------------
extern "C" void kernel_launch(void* const* d_in, const int* in_sizes, int n_in,
                              void* d_out, int out_size) {
    (void)in_sizes; (void)n_in; (void)out_size;
    const float* x  = (const float*)d_in[0];
    const float* bl = (const float*)d_in[1];
    const float* w1 = (const float*)d_in[2];
    const float* b1 = (const float*)d_in[3];
    const float* w2 = (const float*)d_in[4];
    const float* b2 = (const float*)d_in[5];
    const float* w3 = (const float*)d_in[6];
    const float* b3 = (const float*)d_in[7];
    const float* w4 = (const float*)d_in[8];
    const float* b4 = (const float*)d_in[9];
    const float* w5 = (const float*)d_in[10];
    const float* b5 = (const float*)d_in[11];
    const float* w6 = (const float*)d_in[12];
    const float* b6 = (const float*)d_in[13];
    float* out = (float*)d_out;

    void* sync_ptr = nullptr;
    cudaGetSymbolAddress(&sync_ptr, g_sync);
    cudaMemsetAsync(sync_ptr, 0, 49 * sizeof(unsigned));

    spnet_main_kernel<<<NCONVBLK + NGATHER, NTHREADS>>>(
        x, bl, w1, b1, w2, b2, w3, b3, w4, b4, w5, b5, w6, b6, out);
    spnet_paint_kernel<<<NPAINT, NTHREADS>>>(out);
}